// round 14
// baseline (speedup 1.0000x reference)
#include <cuda_runtime.h>
#include <cuda_fp16.h>
#include <string.h>

#define BDIM 4
#define DIMZ 192
#define DIMY 192
#define DIMX 192
#define NTOT (BDIM*DIMZ*DIMY*DIMX)   // 28,311,552
#define YSEG 4
#define YLEN 48
#define ZSEG 12
#define ZLEN 16
#define NPART (DIMY * ZSEG * BDIM)   // 9216

#define C1f 1.0e-4f
#define C2f 9.0e-4f

// Offsets for fp16 intermediate storage (interior means of blurred fields).
#define OFFQ  1.0f
#define OFFR  0.0f
#define OFFQ2 (7.0f / 6.0f)
#define OFFR2 (1.0f / 6.0f)

typedef unsigned long long ull;

// Gaussian weights (sigma=1.5, k=11): compile-time immediates.
__device__ constexpr float GW[11] = {
    0.00102838f, 0.00759876f, 0.03600077f, 0.10936069f, 0.21300554f,
    0.26601172f,
    0.21300554f, 0.10936069f, 0.03600077f, 0.00759876f, 0.00102838f
};

// Intermediate: half4 {Bxy(q)-OFFQ, Bxy(r), Bxy(q^2)-OFFQ2, Bxy(r^2)-OFFR2}
// packed in one ull per voxel, where q = g+p, r = g-p.
__device__ ull   g_h[NTOT];
__device__ float g_part[NPART];

// ---- packed f32x2 helpers -------------------------------------------------
__device__ __forceinline__ ull pk2(float x, float y) {
    ull r; asm("mov.b64 %0, {%1,%2};" : "=l"(r) : "f"(x), "f"(y)); return r;
}
__device__ __forceinline__ void upk2(ull v, float& x, float& y) {
    asm("mov.b64 {%0,%1}, %2;" : "=f"(x), "=f"(y) : "l"(v));
}
__device__ __forceinline__ ull mul2_(ull a, ull b) {
    ull d; asm("mul.rn.f32x2 %0, %1, %2;" : "=l"(d) : "l"(a), "l"(b)); return d;
}
__device__ __forceinline__ ull add2_(ull a, ull b) {
    ull d; asm("add.rn.f32x2 %0, %1, %2;" : "=l"(d) : "l"(a), "l"(b)); return d;
}
__device__ __forceinline__ ull fma2_(ull a, ull b, ull c) {
    ull d; asm("fma.rn.f32x2 %0, %1, %2, %3;" : "=l"(d) : "l"(a), "l"(b), "l"(c));
    return d;
}
__device__ __forceinline__ ull pack_u32(unsigned lo, unsigned hi) {
    ull r; asm("mov.b64 %0, {%1,%2};" : "=l"(r) : "r"(lo), "r"(hi)); return r;
}
__device__ __forceinline__ void unpack_u32(ull v, unsigned& lo, unsigned& hi) {
    asm("mov.b64 {%0,%1}, %2;" : "=r"(lo), "=r"(hi) : "l"(v));
}

// Full clamped raw-row loader (prologue: handles both y boundaries).
__device__ __forceinline__ void load_row_full(const float* __restrict__ gt,
                                              const float* __restrict__ pr,
                                              size_t slice, int yin,
                                              int x1, int x2, bool do2,
                                              float& g1, float& p1,
                                              float& g2, float& p2) {
    const bool yok = (yin >= 0) && (yin < DIMY);
    const int yc = yin < 0 ? 0 : (yin >= DIMY ? DIMY - 1 : yin);
    const size_t rb = slice + (size_t)yc * DIMX;
    const int xc1 = x1 < 0 ? 0 : x1;
    const float a = gt[rb + xc1];
    const float c = pr[rb + xc1];
    const bool ok1 = yok && (x1 >= 0);
    g1 = ok1 ? a : 0.f;
    p1 = ok1 ? c : 0.f;
    g2 = 0.f; p2 = 0.f;
    if (do2) {
        const int xc2 = (x2 < DIMX) ? x2 : (DIMX - 1);
        const float d = gt[rb + xc2];
        const float e = pr[rb + xc2];
        const bool ok2 = yok && (x2 < DIMX);
        g2 = ok2 ? d : 0.f;
        p2 = ok2 ? e : 0.f;
    }
}

// Steady-state loader: yin >= 6 guaranteed, only the high-y clamp needed.
__device__ __forceinline__ void load_row_hi(const float* __restrict__ gt,
                                            const float* __restrict__ pr,
                                            size_t slice, int yin,
                                            int xc1, bool x1ok,
                                            int xc2, bool x2ok, bool do2,
                                            float& g1, float& p1,
                                            float& g2, float& p2) {
    const bool yok = (yin < DIMY);
    const int yc = yok ? yin : (DIMY - 1);
    const size_t rb = slice + (size_t)yc * DIMX;
    const float a = gt[rb + xc1];
    const float c = pr[rb + xc1];
    const bool ok1 = yok && x1ok;
    g1 = ok1 ? a : 0.f;
    p1 = ok1 ? c : 0.f;
    g2 = 0.f; p2 = 0.f;
    if (do2) {
        const float d = gt[rb + xc2];
        const float e = pr[rb + xc2];
        const bool ok2 = yok && x2ok;
        g2 = ok2 ? d : 0.f;
        p2 = ok2 ? e : 0.f;
    }
}

// x-blur with split even/odd accumulator chains (depth 11 -> 6).
__device__ __forceinline__ void xblur_split(const ull* __restrict__ sb, int base,
                                            const ull* __restrict__ vw,
                                            ull zero2, ull& s01, ull& s23) {
    ull s01a = zero2, s23a = zero2;
    ull s01b = zero2, s23b = zero2;
#pragma unroll
    for (int k = 0; k < 11; k += 2) {
        const ull v = sb[base + k];
        const ull t = mul2_(vw[k], v);
        s01a = add2_(s01a, t);
        s23a = fma2_(t, v, s23a);
    }
#pragma unroll
    for (int k = 1; k < 11; k += 2) {
        const ull v = sb[base + k];
        const ull t = mul2_(vw[k], v);
        s01b = add2_(s01b, t);
        s23b = fma2_(t, v, s23b);
    }
    s01 = add2_(s01a, s01b);
    s23 = add2_(s23a, s23b);
}

// ---------------------------------------------------------------------------
// Pass 1: fused (q,r) channel-gen + x-blur + y-blur. Per-warp 32-wide strips,
// one packed (q,r) smem strip, packed f32x2 math, split accumulator chains.
// ---------------------------------------------------------------------------
__global__ void __launch_bounds__(192)
k_xyblur(const float* __restrict__ gt, const float* __restrict__ pr) {
    __shared__ ull sbv[6][2][44];   // packed (q,r) raw rows per warp
    const int tid  = threadIdx.x;
    const int lane = tid & 31;
    const int wrp  = tid >> 5;
    const int xbase = wrp * 32;
    const int x  = xbase + lane;
    const int x1 = xbase - 5 + lane;
    const int x2 = xbase + 27 + lane;
    const bool do2 = (lane < 10);
    const int xc1 = x1 < 0 ? 0 : x1;
    const bool x1ok = (x1 >= 0);
    const int xc2 = (x2 < DIMX) ? x2 : (DIMX - 1);
    const bool x2ok = (x2 < DIMX);
    const int z  = blockIdx.x;
    const int ys = blockIdx.y * YLEN;
    const int b  = blockIdx.z;
    const size_t slice = (((size_t)b * DIMZ + z) * DIMY) * DIMX;

    const ull vw0 = pk2(GW[0], GW[0]);
    const ull vw1 = pk2(GW[1], GW[1]);
    const ull vw2 = pk2(GW[2], GW[2]);
    const ull vw3 = pk2(GW[3], GW[3]);
    const ull vw4 = pk2(GW[4], GW[4]);
    const ull vw5 = pk2(GW[5], GW[5]);
    const ull vw[11] = {vw0,vw1,vw2,vw3,vw4,vw5,vw4,vw3,vw2,vw1,vw0};

    const ull zero2 = pk2(0.f, 0.f);
    ull win01[11], win23[11];
#pragma unroll
    for (int s = 0; s < 11; ++s) { win01[s] = zero2; win23[s] = zero2; }

    float g1, p1, g2, p2;
    load_row_full(gt, pr, slice, ys - 5, x1, x2, do2, g1, p1, g2, p2);

    // Prologue: rows yin = ys-5+u for u = 0..9 -> ring slot u.
#pragma unroll
    for (int u = 0; u < 10; ++u) {
        const int buf = u & 1;
        sbv[wrp][buf][lane] = pk2(g1 + p1, g1 - p1);
        if (do2) sbv[wrp][buf][32 + lane] = pk2(g2 + p2, g2 - p2);
        __syncwarp();
        load_row_full(gt, pr, slice, ys - 4 + u, x1, x2, do2, g1, p1, g2, p2);

        ull s01, s23;
        xblur_split(sbv[wrp][buf], lane, vw, zero2, s01, s23);
        win01[u] = s01; win23[u] = s23;
    }

    // Main: outputs j = 0..YLEN-1 (y = ys+j); insert row yin = ys+j+5.
#pragma unroll
    for (int jb = 0; jb < YLEN; jb += 11) {
#pragma unroll
        for (int i = 0; i < 11; ++i) {
            const int j = jb + i;
            if (j < YLEN) {
                const int buf = j & 1;   // continues prologue alternation
                sbv[wrp][buf][lane] = pk2(g1 + p1, g1 - p1);
                if (do2) sbv[wrp][buf][32 + lane] = pk2(g2 + p2, g2 - p2);
                __syncwarp();
                load_row_hi(gt, pr, slice, ys + j + 6,
                            xc1, x1ok, xc2, x2ok, do2, g1, p1, g2, p2);

                // x-blur -> ring slot (i+10)%11 (static per i).
                const int slot = (i + 10) % 11;
                {
                    ull s01, s23;
                    xblur_split(sbv[wrp][buf], lane, vw, zero2, s01, s23);
                    win01[slot] = s01; win23[slot] = s23;
                }

                // y-blur: tap t uses slot (i+t)%11 (static); split chains.
                ull m01a = zero2, m23a = zero2;
                ull m01b = zero2, m23b = zero2;
#pragma unroll
                for (int t = 0; t < 11; t += 2) {
                    const int s = (i + t) % 11;
                    m01a = fma2_(vw[t], win01[s], m01a);
                    m23a = fma2_(vw[t], win23[s], m23a);
                }
#pragma unroll
                for (int t = 1; t < 11; t += 2) {
                    const int s = (i + t) % 11;
                    m01b = fma2_(vw[t], win01[s], m01b);
                    m23b = fma2_(vw[t], win23[s], m23b);
                }
                const ull m01 = add2_(m01a, m01b);
                const ull m23 = add2_(m23a, m23b);
                float f0, f1, f2, f3;
                upk2(m01, f0, f1);
                upk2(m23, f2, f3);
                const __half2 h01 = __floats2half2_rn(f0 - OFFQ,  f1 - OFFR);
                const __half2 h23 = __floats2half2_rn(f2 - OFFQ2, f3 - OFFR2);
                unsigned u01, u23;
                memcpy(&u01, &h01, 4);
                memcpy(&u23, &h23, 4);
                const size_t oidx = slice + (size_t)(ys + j) * DIMX + x;
                g_h[oidx] = pack_u32(u01, u23);
            }
        }
    }
}

// ---------------------------------------------------------------------------
// Pass 2: z-blur + SSIM + block-partial reduction (12 z-segments of 16).
// One LDG.64 per insert; -OFF fill for invalid z taps; depth-1 prefetch;
// split accumulator chains.
// ---------------------------------------------------------------------------
__global__ void __launch_bounds__(192, 4) k_zssim() {
    const int x = threadIdx.x;
    const int y = blockIdx.x;
    const int zs = blockIdx.y * ZLEN;
    const int b = blockIdx.z;

    const size_t colbase = (((size_t)b * DIMZ) * DIMY + y) * DIMX + x;
    const size_t zstride = (size_t)DIMY * DIMX;

    const ull vw0 = pk2(GW[0], GW[0]);
    const ull vw1 = pk2(GW[1], GW[1]);
    const ull vw2 = pk2(GW[2], GW[2]);
    const ull vw3 = pk2(GW[3], GW[3]);
    const ull vw4 = pk2(GW[4], GW[4]);
    const ull vw5 = pk2(GW[5], GW[5]);
    const ull vw[11] = {vw0,vw1,vw2,vw3,vw4,vw5,vw4,vw3,vw2,vw1,vw0};

    const ull n01 = pk2(-OFFQ,  -OFFR);
    const ull n23 = pk2(-OFFQ2, -OFFR2);
    const ull zero2 = pk2(0.f, 0.f);

    ull win01[11], win23[11];

    // Prologue: u = 0..9 -> zin = zs-5+u (clamped; -OFF fill when invalid).
#pragma unroll
    for (int u = 0; u < 10; ++u) {
        const int zin = zs - 5 + u;
        const int zc = (zin >= 0) ? zin : 0;
        const size_t off = colbase + (size_t)zc * zstride;
        const ull raw = g_h[off];
        unsigned u01, u23;
        unpack_u32(raw, u01, u23);
        __half2 h01, h23;
        memcpy(&h01, &u01, 4);
        memcpy(&h23, &u23, 4);
        const float2 a = __half22float2(h01);
        const float2 c = __half22float2(h23);
        const bool ok = (zin >= 0);
        win01[u] = ok ? pk2(a.x, a.y) : n01;
        win23[u] = ok ? pk2(c.x, c.y) : n23;
    }

    // Prefetch u = 10 (zin = zs+5, always valid: <= 181).
    ull pf01, pf23;
    {
        const size_t off = colbase + (size_t)(zs + 5) * zstride;
        const ull raw = g_h[off];
        unsigned u01, u23;
        unpack_u32(raw, u01, u23);
        __half2 h01, h23;
        memcpy(&h01, &u01, 4);
        memcpy(&h23, &u23, 4);
        const float2 a = __half22float2(h01);
        const float2 c = __half22float2(h23);
        pf01 = pk2(a.x, a.y);
        pf23 = pk2(c.x, c.y);
    }

    float acc = 0.f;
#pragma unroll
    for (int jb = 0; jb < ZLEN; jb += 11) {
#pragma unroll
        for (int i = 0; i < 11; ++i) {
            const int j = jb + i;
            if (j < ZLEN) {
                const int slot = (i + 10) % 11;
                win01[slot] = pf01; win23[slot] = pf23;

                // Prefetch u = j+11 (zin = zs+j+6), clamped + -OFF select.
                {
                    const int zin = zs + j + 6;
                    const int zc = (zin < DIMZ) ? zin : (DIMZ - 1);
                    const size_t off = colbase + (size_t)zc * zstride;
                    const ull raw = g_h[off];
                    unsigned u01, u23;
                    unpack_u32(raw, u01, u23);
                    __half2 h01, h23;
                    memcpy(&h01, &u01, 4);
                    memcpy(&h23, &u23, 4);
                    const float2 a = __half22float2(h01);
                    const float2 c = __half22float2(h23);
                    const bool ok = (zin < DIMZ);
                    pf01 = ok ? pk2(a.x, a.y) : n01;
                    pf23 = ok ? pk2(c.x, c.y) : n23;
                }

                ull m01a = zero2, m23a = zero2;
                ull m01b = zero2, m23b = zero2;
#pragma unroll
                for (int t = 0; t < 11; t += 2) {
                    const int s = (i + t) % 11;   // static
                    m01a = fma2_(vw[t], win01[s], m01a);
                    m23a = fma2_(vw[t], win23[s], m23a);
                }
#pragma unroll
                for (int t = 1; t < 11; t += 2) {
                    const int s = (i + t) % 11;   // static
                    m01b = fma2_(vw[t], win01[s], m01b);
                    m23b = fma2_(vw[t], win23[s], m23b);
                }
                const ull m01 = add2_(m01a, m01b);
                const ull m23 = add2_(m23a, m23b);
                float mq, mr, mq2, mr2;
                upk2(m01, mq, mr);
                upk2(m23, mq2, mr2);
                const float Bq  = mq  + OFFQ;
                const float Br  = mr  + OFFR;
                const float Bq2 = mq2 + OFFQ2;
                const float Br2 = mr2 + OFFR2;
                const float mux = 0.5f * (Bq + Br);
                const float muy = 0.5f * (Bq - Br);
                const float mux2 = mux * mux;
                const float muy2 = muy * muy;
                const float muxy = mux * muy;
                const float E2sum = 0.5f  * (Bq2 + Br2);  // E[g^2]+E[p^2]
                const float Egp   = 0.25f * (Bq2 - Br2);  // E[g*p]
                const float sxsy = E2sum - mux2 - muy2;   // sigx^2 + sigy^2
                const float sxy  = Egp - muxy;
                const float num = (2.f * muxy + C1f) * (2.f * sxy + C2f);
                const float den = (mux2 + muy2 + C1f) * (sxsy + C2f);
                acc += 1.f - __fdividef(num, den);
            }
        }
    }

    __shared__ float red[6];
    float v = acc;
#pragma unroll
    for (int o = 16; o > 0; o >>= 1)
        v += __shfl_down_sync(0xffffffffu, v, o);
    const int wid = threadIdx.x >> 5;
    if ((threadIdx.x & 31) == 0) red[wid] = v;
    __syncthreads();
    if (threadIdx.x == 0) {
        float t = 0.f;
#pragma unroll
        for (int w = 0; w < 6; ++w) t += red[w];
        const int bn = blockIdx.x + DIMY * (blockIdx.y + ZSEG * blockIdx.z);
        g_part[bn] = t;
    }
}

// ---------------------------------------------------------------------------
__global__ void __launch_bounds__(256) k_final(float* __restrict__ out) {
    __shared__ double red[8];
    double s = 0.0;
    for (int i = threadIdx.x; i < NPART; i += 256)
        s += (double)g_part[i];
#pragma unroll
    for (int o = 16; o > 0; o >>= 1)
        s += __shfl_down_sync(0xffffffffu, s, o);
    if ((threadIdx.x & 31) == 0) red[threadIdx.x >> 5] = s;
    __syncthreads();
    if (threadIdx.x == 0) {
        double t = 0.0;
#pragma unroll
        for (int w = 0; w < 8; ++w) t += red[w];
        out[0] = (float)(t * (1.0 / (double)NTOT));
    }
}

// ---------------------------------------------------------------------------
extern "C" void kernel_launch(void* const* d_in, const int* in_sizes, int n_in,
                              void* d_out, int out_size) {
    const float* gt = (const float*)d_in[0];
    const float* pr = (const float*)d_in[1];
    float* out = (float*)d_out;

    k_xyblur<<<dim3(DIMZ, YSEG, BDIM), 192>>>(gt, pr);
    k_zssim<<<dim3(DIMY, ZSEG, BDIM), 192>>>();
    k_final<<<1, 256>>>(out);
}

// round 15
// speedup vs baseline: 1.1604x; 1.1604x over previous
#include <cuda_runtime.h>
#include <cuda_fp16.h>
#include <string.h>

#define BDIM 4
#define DIMZ 192
#define DIMY 192
#define DIMX 192
#define NTOT (BDIM*DIMZ*DIMY*DIMX)   // 28,311,552
#define YSEG 4
#define YLEN 48
#define ZSEG 12
#define ZLEN 16
#define NBLK_Z (DIMY * ZSEG * BDIM)  // 9216 zssim blocks

#define C1f 1.0e-4f
#define C2f 9.0e-4f

// Offsets for fp16 intermediate storage (interior means of blurred fields).
#define OFFQ  1.0f
#define OFFR  0.0f
#define OFFQ2 (7.0f / 6.0f)
#define OFFR2 (1.0f / 6.0f)

typedef unsigned long long ull;

// Gaussian weights (sigma=1.5, k=11): compile-time immediates.
__device__ constexpr float GW[11] = {
    0.00102838f, 0.00759876f, 0.03600077f, 0.10936069f, 0.21300554f,
    0.26601172f,
    0.21300554f, 0.10936069f, 0.03600077f, 0.00759876f, 0.00102838f
};

// Intermediate: half4 {Bxy(q)-OFFQ, Bxy(r), Bxy(q^2)-OFFQ2, Bxy(r^2)-OFFR2}
// packed in one ull per voxel, where q = g+p, r = g-p.
__device__ ull    g_h[NTOT];
__device__ double g_acc;     // zero-init; reset by last block each run
__device__ int    g_count;   // zero-init; reset by last block each run

// ---- packed f32x2 helpers -------------------------------------------------
__device__ __forceinline__ ull pk2(float x, float y) {
    ull r; asm("mov.b64 %0, {%1,%2};" : "=l"(r) : "f"(x), "f"(y)); return r;
}
__device__ __forceinline__ void upk2(ull v, float& x, float& y) {
    asm("mov.b64 {%0,%1}, %2;" : "=f"(x), "=f"(y) : "l"(v));
}
__device__ __forceinline__ ull mul2_(ull a, ull b) {
    ull d; asm("mul.rn.f32x2 %0, %1, %2;" : "=l"(d) : "l"(a), "l"(b)); return d;
}
__device__ __forceinline__ ull add2_(ull a, ull b) {
    ull d; asm("add.rn.f32x2 %0, %1, %2;" : "=l"(d) : "l"(a), "l"(b)); return d;
}
__device__ __forceinline__ ull fma2_(ull a, ull b, ull c) {
    ull d; asm("fma.rn.f32x2 %0, %1, %2, %3;" : "=l"(d) : "l"(a), "l"(b), "l"(c));
    return d;
}
__device__ __forceinline__ ull pack_u32(unsigned lo, unsigned hi) {
    ull r; asm("mov.b64 %0, {%1,%2};" : "=l"(r) : "r"(lo), "r"(hi)); return r;
}
__device__ __forceinline__ void unpack_u32(ull v, unsigned& lo, unsigned& hi) {
    asm("mov.b64 {%0,%1}, %2;" : "=r"(lo), "=r"(hi) : "l"(v));
}

// Full clamped raw-row loader (prologue: handles both y boundaries).
__device__ __forceinline__ void load_row_full(const float* __restrict__ gt,
                                              const float* __restrict__ pr,
                                              size_t slice, int yin,
                                              int x1, int x2, bool do2,
                                              float& g1, float& p1,
                                              float& g2, float& p2) {
    const bool yok = (yin >= 0) && (yin < DIMY);
    const int yc = yin < 0 ? 0 : (yin >= DIMY ? DIMY - 1 : yin);
    const size_t rb = slice + (size_t)yc * DIMX;
    const int xc1 = x1 < 0 ? 0 : x1;
    const float a = gt[rb + xc1];
    const float c = pr[rb + xc1];
    const bool ok1 = yok && (x1 >= 0);
    g1 = ok1 ? a : 0.f;
    p1 = ok1 ? c : 0.f;
    g2 = 0.f; p2 = 0.f;
    if (do2) {
        const int xc2 = (x2 < DIMX) ? x2 : (DIMX - 1);
        const float d = gt[rb + xc2];
        const float e = pr[rb + xc2];
        const bool ok2 = yok && (x2 < DIMX);
        g2 = ok2 ? d : 0.f;
        p2 = ok2 ? e : 0.f;
    }
}

// Steady-state loader: yin >= 6 guaranteed, only the high-y clamp needed.
__device__ __forceinline__ void load_row_hi(const float* __restrict__ gt,
                                            const float* __restrict__ pr,
                                            size_t slice, int yin,
                                            int xc1, bool x1ok,
                                            int xc2, bool x2ok, bool do2,
                                            float& g1, float& p1,
                                            float& g2, float& p2) {
    const bool yok = (yin < DIMY);
    const int yc = yok ? yin : (DIMY - 1);
    const size_t rb = slice + (size_t)yc * DIMX;
    const float a = gt[rb + xc1];
    const float c = pr[rb + xc1];
    const bool ok1 = yok && x1ok;
    g1 = ok1 ? a : 0.f;
    p1 = ok1 ? c : 0.f;
    g2 = 0.f; p2 = 0.f;
    if (do2) {
        const float d = gt[rb + xc2];
        const float e = pr[rb + xc2];
        const bool ok2 = yok && x2ok;
        g2 = ok2 ? d : 0.f;
        p2 = ok2 ? e : 0.f;
    }
}

// ---------------------------------------------------------------------------
// Pass 1: fused (q,r) channel-gen + x-blur + y-blur. Per-warp 32-wide strips,
// one packed (q,r) smem strip (8 B/tap LDS), fully packed f32x2 math:
// per tap mul2/add2/fma2 gives blur(q),blur(r),blur(q^2),blur(r^2).
// (R13 measured-best body; output stores use streaming hint.)
// ---------------------------------------------------------------------------
__global__ void __launch_bounds__(192)
k_xyblur(const float* __restrict__ gt, const float* __restrict__ pr) {
    __shared__ ull sbv[6][2][44];   // packed (q,r) raw rows per warp
    const int tid  = threadIdx.x;
    const int lane = tid & 31;
    const int wrp  = tid >> 5;
    const int xbase = wrp * 32;
    const int x  = xbase + lane;
    const int x1 = xbase - 5 + lane;
    const int x2 = xbase + 27 + lane;
    const bool do2 = (lane < 10);
    const int xc1 = x1 < 0 ? 0 : x1;
    const bool x1ok = (x1 >= 0);
    const int xc2 = (x2 < DIMX) ? x2 : (DIMX - 1);
    const bool x2ok = (x2 < DIMX);
    const int z  = blockIdx.x;
    const int ys = blockIdx.y * YLEN;
    const int b  = blockIdx.z;
    const size_t slice = (((size_t)b * DIMZ + z) * DIMY) * DIMX;

    const ull vw0 = pk2(GW[0], GW[0]);
    const ull vw1 = pk2(GW[1], GW[1]);
    const ull vw2 = pk2(GW[2], GW[2]);
    const ull vw3 = pk2(GW[3], GW[3]);
    const ull vw4 = pk2(GW[4], GW[4]);
    const ull vw5 = pk2(GW[5], GW[5]);
    const ull vw[11] = {vw0,vw1,vw2,vw3,vw4,vw5,vw4,vw3,vw2,vw1,vw0};

    const ull zero2 = pk2(0.f, 0.f);
    ull win01[11], win23[11];
#pragma unroll
    for (int s = 0; s < 11; ++s) { win01[s] = zero2; win23[s] = zero2; }

    float g1, p1, g2, p2;
    load_row_full(gt, pr, slice, ys - 5, x1, x2, do2, g1, p1, g2, p2);

    // Prologue: rows yin = ys-5+u for u = 0..9 -> ring slot u.
#pragma unroll
    for (int u = 0; u < 10; ++u) {
        const int buf = u & 1;
        sbv[wrp][buf][lane] = pk2(g1 + p1, g1 - p1);
        if (do2) sbv[wrp][buf][32 + lane] = pk2(g2 + p2, g2 - p2);
        __syncwarp();
        load_row_full(gt, pr, slice, ys - 4 + u, x1, x2, do2, g1, p1, g2, p2);

        ull s01 = zero2, s23 = zero2;
#pragma unroll
        for (int k = 0; k < 11; ++k) {
            const ull v = sbv[wrp][buf][lane + k];
            const ull t = mul2_(vw[k], v);
            s01 = add2_(s01, t);
            s23 = fma2_(t, v, s23);
        }
        win01[u] = s01; win23[u] = s23;
    }

    // Main: outputs j = 0..YLEN-1 (y = ys+j); insert row yin = ys+j+5.
#pragma unroll
    for (int jb = 0; jb < YLEN; jb += 11) {
#pragma unroll
        for (int i = 0; i < 11; ++i) {
            const int j = jb + i;
            if (j < YLEN) {
                const int buf = j & 1;   // continues prologue alternation
                sbv[wrp][buf][lane] = pk2(g1 + p1, g1 - p1);
                if (do2) sbv[wrp][buf][32 + lane] = pk2(g2 + p2, g2 - p2);
                __syncwarp();
                load_row_hi(gt, pr, slice, ys + j + 6,
                            xc1, x1ok, xc2, x2ok, do2, g1, p1, g2, p2);

                // x-blur -> ring slot (i+10)%11 (static per i).
                const int slot = (i + 10) % 11;
                {
                    ull s01 = zero2, s23 = zero2;
#pragma unroll
                    for (int k = 0; k < 11; ++k) {
                        const ull v = sbv[wrp][buf][lane + k];
                        const ull t = mul2_(vw[k], v);
                        s01 = add2_(s01, t);
                        s23 = fma2_(t, v, s23);
                    }
                    win01[slot] = s01; win23[slot] = s23;
                }

                // y-blur: tap t uses slot (i+t)%11 (static).
                ull m01 = zero2, m23 = zero2;
#pragma unroll
                for (int t = 0; t < 11; ++t) {
                    const int s = (i + t) % 11;
                    m01 = fma2_(vw[t], win01[s], m01);
                    m23 = fma2_(vw[t], win23[s], m23);
                }
                float f0, f1, f2, f3;
                upk2(m01, f0, f1);
                upk2(m23, f2, f3);
                const __half2 h01 = __floats2half2_rn(f0 - OFFQ,  f1 - OFFR);
                const __half2 h23 = __floats2half2_rn(f2 - OFFQ2, f3 - OFFR2);
                unsigned u01, u23;
                memcpy(&u01, &h01, 4);
                memcpy(&u23, &h23, 4);
                const size_t oidx = slice + (size_t)(ys + j) * DIMX + x;
                __stcs((ull*)&g_h[oidx], pack_u32(u01, u23));
            }
        }
    }
}

// ---------------------------------------------------------------------------
// Pass 2: z-blur + SSIM + reduction (12 z-segments of 16). One streaming
// LDG.64 per insert; -OFF fill for invalid z taps; depth-1 prefetch.
// Last-block-done pattern writes the final mean (no separate kernel).
// ---------------------------------------------------------------------------
__global__ void __launch_bounds__(192, 4) k_zssim(float* __restrict__ out) {
    const int x = threadIdx.x;
    const int y = blockIdx.x;
    const int zs = blockIdx.y * ZLEN;
    const int b = blockIdx.z;

    const size_t colbase = (((size_t)b * DIMZ) * DIMY + y) * DIMX + x;
    const size_t zstride = (size_t)DIMY * DIMX;

    const ull vw0 = pk2(GW[0], GW[0]);
    const ull vw1 = pk2(GW[1], GW[1]);
    const ull vw2 = pk2(GW[2], GW[2]);
    const ull vw3 = pk2(GW[3], GW[3]);
    const ull vw4 = pk2(GW[4], GW[4]);
    const ull vw5 = pk2(GW[5], GW[5]);
    const ull vw[11] = {vw0,vw1,vw2,vw3,vw4,vw5,vw4,vw3,vw2,vw1,vw0};

    const ull n01 = pk2(-OFFQ,  -OFFR);
    const ull n23 = pk2(-OFFQ2, -OFFR2);
    const ull zero2 = pk2(0.f, 0.f);

    ull win01[11], win23[11];

    // Prologue: u = 0..9 -> zin = zs-5+u (clamped; -OFF fill when invalid).
#pragma unroll
    for (int u = 0; u < 10; ++u) {
        const int zin = zs - 5 + u;
        const int zc = (zin >= 0) ? zin : 0;
        const size_t off = colbase + (size_t)zc * zstride;
        const ull raw = __ldcs((const ull*)&g_h[off]);
        unsigned u01, u23;
        unpack_u32(raw, u01, u23);
        __half2 h01, h23;
        memcpy(&h01, &u01, 4);
        memcpy(&h23, &u23, 4);
        const float2 a = __half22float2(h01);
        const float2 c = __half22float2(h23);
        const bool ok = (zin >= 0);
        win01[u] = ok ? pk2(a.x, a.y) : n01;
        win23[u] = ok ? pk2(c.x, c.y) : n23;
    }

    // Prefetch u = 10 (zin = zs+5, always valid: <= 181).
    ull pf01, pf23;
    {
        const size_t off = colbase + (size_t)(zs + 5) * zstride;
        const ull raw = __ldcs((const ull*)&g_h[off]);
        unsigned u01, u23;
        unpack_u32(raw, u01, u23);
        __half2 h01, h23;
        memcpy(&h01, &u01, 4);
        memcpy(&h23, &u23, 4);
        const float2 a = __half22float2(h01);
        const float2 c = __half22float2(h23);
        pf01 = pk2(a.x, a.y);
        pf23 = pk2(c.x, c.y);
    }

    float acc = 0.f;
#pragma unroll
    for (int jb = 0; jb < ZLEN; jb += 11) {
#pragma unroll
        for (int i = 0; i < 11; ++i) {
            const int j = jb + i;
            if (j < ZLEN) {
                const int slot = (i + 10) % 11;
                win01[slot] = pf01; win23[slot] = pf23;

                // Prefetch u = j+11 (zin = zs+j+6), clamped + -OFF select.
                {
                    const int zin = zs + j + 6;
                    const int zc = (zin < DIMZ) ? zin : (DIMZ - 1);
                    const size_t off = colbase + (size_t)zc * zstride;
                    const ull raw = __ldcs((const ull*)&g_h[off]);
                    unsigned u01, u23;
                    unpack_u32(raw, u01, u23);
                    __half2 h01, h23;
                    memcpy(&h01, &u01, 4);
                    memcpy(&h23, &u23, 4);
                    const float2 a = __half22float2(h01);
                    const float2 c = __half22float2(h23);
                    const bool ok = (zin < DIMZ);
                    pf01 = ok ? pk2(a.x, a.y) : n01;
                    pf23 = ok ? pk2(c.x, c.y) : n23;
                }

                ull m01 = zero2, m23 = zero2;
#pragma unroll
                for (int t = 0; t < 11; ++t) {
                    const int s = (i + t) % 11;   // static
                    m01 = fma2_(vw[t], win01[s], m01);
                    m23 = fma2_(vw[t], win23[s], m23);
                }
                float mq, mr, mq2, mr2;
                upk2(m01, mq, mr);
                upk2(m23, mq2, mr2);
                const float Bq  = mq  + OFFQ;
                const float Br  = mr  + OFFR;
                const float Bq2 = mq2 + OFFQ2;
                const float Br2 = mr2 + OFFR2;
                const float mux = 0.5f * (Bq + Br);
                const float muy = 0.5f * (Bq - Br);
                const float mux2 = mux * mux;
                const float muy2 = muy * muy;
                const float muxy = mux * muy;
                const float E2sum = 0.5f  * (Bq2 + Br2);  // E[g^2]+E[p^2]
                const float Egp   = 0.25f * (Bq2 - Br2);  // E[g*p]
                const float sxsy = E2sum - mux2 - muy2;   // sigx^2 + sigy^2
                const float sxy  = Egp - muxy;
                const float num = (2.f * muxy + C1f) * (2.f * sxy + C2f);
                const float den = (mux2 + muy2 + C1f) * (sxsy + C2f);
                acc += 1.f - __fdividef(num, den);
            }
        }
    }

    // Block reduction, then global accumulate + last-block finalize.
    __shared__ float red[6];
    float v = acc;
#pragma unroll
    for (int o = 16; o > 0; o >>= 1)
        v += __shfl_down_sync(0xffffffffu, v, o);
    const int wid = threadIdx.x >> 5;
    if ((threadIdx.x & 31) == 0) red[wid] = v;
    __syncthreads();
    if (threadIdx.x == 0) {
        float t = 0.f;
#pragma unroll
        for (int w = 0; w < 6; ++w) t += red[w];
        atomicAdd(&g_acc, (double)t);
        __threadfence();
        const int done = atomicAdd(&g_count, 1);
        if (done == NBLK_Z - 1) {
            // All other blocks' g_acc adds are visible (fence + atomic order).
            const double total = g_acc;
            out[0] = (float)(total * (1.0 / (double)NTOT));
            // Reset for the next graph replay.
            g_acc = 0.0;
            __threadfence();
            g_count = 0;
        }
    }
}

// ---------------------------------------------------------------------------
extern "C" void kernel_launch(void* const* d_in, const int* in_sizes, int n_in,
                              void* d_out, int out_size) {
    const float* gt = (const float*)d_in[0];
    const float* pr = (const float*)d_in[1];
    float* out = (float*)d_out;

    k_xyblur<<<dim3(DIMZ, YSEG, BDIM), 192>>>(gt, pr);
    k_zssim<<<dim3(DIMY, ZSEG, BDIM), 192>>>(out);
}